// round 15
// baseline (speedup 1.0000x reference)
#include <cuda_runtime.h>
#include <cuda_bf16.h>

#define N      512
#define DIM    256
#define EPSV   1e-12f
#define KLOG2E 14.426950408889634f   // SCAL(=10) * log2(e)

#define NTILE  136                   // 16*17/2 triangular 32x32 tiles
#define NBLK   272                   // 2 half-tile blocks per tile
#define CONS   128                   // blocks 0..127 also consume 4 anchors
#define ASP    36                    // As pitch (floats), 144B = 9*16B
#define BSP    36

__device__ float    g_D[N * N];
__device__ float    g_partial[CONS];
__device__ float    g_pcount[CONS];
__device__ unsigned g_stripe[16];    // per-row-stripe counters (target 32)
__device__ unsigned g_done = 0;

typedef unsigned long long ull;

__device__ __forceinline__ ull ffma2(ull a, ull b, ull c) {
    ull d; asm("fma.rn.f32x2 %0, %1, %2, %3;" : "=l"(d) : "l"(a), "l"(b), "l"(c));
    return d;
}
__device__ __forceinline__ ull addf2(ull a, ull b) {
    ull d; asm("add.rn.f32x2 %0, %1, %2;" : "=l"(d) : "l"(a), "l"(b));
    return d;
}
__device__ __forceinline__ void unpack2(ull v, float& lo, float& hi) {
    asm("mov.b64 {%0, %1}, %2;" : "=f"(lo), "=f"(hi) : "l"(v));
}
__device__ __forceinline__ float ex2a(float x) {
    float y; asm("ex2.approx.ftz.f32 %0, %1;" : "=f"(y) : "f"(x)); return y;
}
__device__ __forceinline__ float rcpa(float x) {
    float y; asm("rcp.approx.ftz.f32 %0, %1;" : "=f"(y) : "f"(x)); return y;
}
__device__ __forceinline__ unsigned ldacq(const unsigned* p) {
    unsigned v;
    asm volatile("ld.acquire.gpu.global.u32 %0, [%1];" : "=r"(v) : "l"(p) : "memory");
    return v;
}
__device__ __forceinline__ void red_release(unsigned* p) {
    asm volatile("red.release.gpu.global.add.u32 [%0], %1;" :: "l"(p), "r"(1u) : "memory");
}
__device__ __forceinline__ unsigned atom_acqrel(unsigned* p) {
    unsigned old;
    asm volatile("atom.acq_rel.gpu.global.add.u32 %0, [%1], %2;"
                 : "=r"(old) : "l"(p), "r"(1u) : "memory");
    return old;
}

// shared-memory pool (phase-1 layout; stg and phase-2 overlay the As region)
#define OFF_AS   0            // float[128][36]  18432 B
#define OFF_BT   18432        // float[128][36]  18432 B
#define OFF_SQI  36864        // float[16]
#define OFF_SQJ  36928        // float[32]
#define POOL_SZ  37120
// overlays (each use separated by __syncthreads)
#define OFF_STG  0            // ull [7][64][4]  14336 B  (combine)
#define OFF_POSQ 0            // float[4][4][64]  4096 B  (phase 2)
#define OFF_QCNT 4096
#define OFF_QSAM 4160
#define OFF_WACC 4224
#define OFF_LAST 4288

__global__ void __launch_bounds__(512, 2)
k_fused(const float* __restrict__ feat, const int* __restrict__ y,
        float* __restrict__ out) {
    __shared__ __align__(16) unsigned char pool[POOL_SZ];

    float* As  = reinterpret_cast<float*>(pool + OFF_AS);
    float* Bt  = reinterpret_cast<float*>(pool + OFF_BT);
    float* sqi = reinterpret_cast<float*>(pool + OFF_SQI);
    float* sqj = reinterpret_cast<float*>(pool + OFF_SQJ);

    const int tid  = threadIdx.x;
    const int bid  = blockIdx.x;
    const int warp = tid >> 5;
    const int lane = tid & 31;

    const float4* f4 = reinterpret_cast<const float4*>(feat);   // row pitch 64

    // =================== PHASE 1: one 16x32 half-tile ===================
    const int hb = bid & 1;
    const int tb = bid >> 1;
    int ti = (int)((sqrtf(8.f * tb + 1.f) - 1.f) * 0.5f);
    if ((ti + 1) * (ti + 2) / 2 <= tb) ++ti;
    if (ti * (ti + 1) / 2 > tb) --ti;
    const int tj = tb - ti * (ti + 1) / 2;
    const int i0 = ti * 32 + hb * 16;    // 16 i-rows
    const int j0 = tj * 32;              // 32 j-rows

    // squared norms: 48 rows, 8 threads each (threads 0..383)
    if (tid < 384) {
        const int r = tid >> 3, q = tid & 7;
        const int grow = (r < 16) ? (i0 + r) : (j0 + r - 16);
        float s = 0.f;
        #pragma unroll
        for (int u = 0; u < 8; ++u) {
            const float4 v = __ldg(&f4[grow * 64 + q * 8 + u]);
            s += v.x * v.x + v.y * v.y + v.z * v.z + v.w * v.w;
        }
        s += __shfl_xor_sync(0xffffffffu, s, 1);
        s += __shfl_xor_sync(0xffffffffu, s, 2);
        s += __shfl_xor_sync(0xffffffffu, s, 4);
        if (q == 0) { if (r < 16) sqi[r] = s; else sqj[r - 16] = s; }
    }

    const int ke      = tid >> 6;        // k-eighth 0..7 (32 k each)
    const int spatial = tid & 63;
    const int ig      = spatial >> 3;    // rows 2ig, 2ig+1 (of 16)
    const int jg      = spatial & 7;     // cols 4jg..4jg+3 (of 32)

    // staging maps (conflict-aware: row varies fastest within a warp)
    const int kfA = tid >> 4,  rowA = tid & 15;   // A: 512 f4, 1/thread
    ull acc00 = 0, acc01 = 0, acc10 = 0, acc11 = 0;

    for (int r = 0; r < 2; ++r) {        // two 128-k rounds
        if (r) __syncthreads();          // round-0 smem reads complete
        {   // stage A (duplicated (a,a), k-major): 2-way conflicts max
            const float4 a = __ldg(&f4[(i0 + rowA) * 64 + r * 32 + kfA]);
            const float av[4] = {a.x, a.y, a.z, a.w};
            #pragma unroll
            for (int e = 0; e < 4; ++e) {
                As[(4 * kfA + e) * ASP + 2 * rowA]     = av[e];
                As[(4 * kfA + e) * ASP + 2 * rowA + 1] = av[e];
            }
        }
        #pragma unroll
        for (int s = 0; s < 2; ++s) {    // stage B (k-major): conflict-free
            const int v = tid + 512 * s;
            const int kfB = v >> 5, rowB = v & 31;
            const float4 b = __ldg(&f4[(j0 + rowB) * 64 + r * 32 + kfB]);
            const float bv[4] = {b.x, b.y, b.z, b.w};
            #pragma unroll
            for (int e = 0; e < 4; ++e)
                Bt[(4 * kfB + e) * BSP + rowB] = bv[e];
        }
        __syncthreads();

        const float* Ab = As + 4 * ig;
        const float* Bb = Bt + 4 * jg;
        const int base = ke * 16;
        #pragma unroll
        for (int k = 0; k < 16; ++k) {
            const int kl = base + k;
            const ulonglong2 a = *reinterpret_cast<const ulonglong2*>(Ab + kl * ASP);
            const ulonglong2 b = *reinterpret_cast<const ulonglong2*>(Bb + kl * BSP);
            acc00 = ffma2(a.x, b.x, acc00);
            acc01 = ffma2(a.x, b.y, acc01);
            acc10 = ffma2(a.y, b.x, acc10);
            acc11 = ffma2(a.y, b.y, acc11);
        }
    }
    __syncthreads();                     // As reads done -> stg overlay safe

    // combine 8 k-eighths via smem (overlay on As region)
    ull (*stg)[64][4] = reinterpret_cast<ull(*)[64][4]>(pool + OFF_STG);
    if (ke >= 1) {
        *reinterpret_cast<ulonglong2*>(&stg[ke - 1][spatial][0]) =
            make_ulonglong2(acc00, acc01);
        *reinterpret_cast<ulonglong2*>(&stg[ke - 1][spatial][2]) =
            make_ulonglong2(acc10, acc11);
    }
    __syncthreads();
    if (ke == 0) {
        #pragma unroll
        for (int s = 0; s < 7; ++s) {
            const ulonglong2 p0 = *reinterpret_cast<const ulonglong2*>(&stg[s][spatial][0]);
            const ulonglong2 p1 = *reinterpret_cast<const ulonglong2*>(&stg[s][spatial][2]);
            acc00 = addf2(acc00, p0.x);
            acc01 = addf2(acc01, p0.y);
            acc10 = addf2(acc10, p1.x);
            acc11 = addf2(acc11, p1.y);
        }
        float d[2][4];
        unpack2(acc00, d[0][0], d[0][1]); unpack2(acc01, d[0][2], d[0][3]);
        unpack2(acc10, d[1][0], d[1][1]); unpack2(acc11, d[1][2], d[1][3]);
        #pragma unroll
        for (int rr = 0; rr < 2; ++rr) {
            const int   orow = 2 * ig + rr;          // 0..15
            const int   gi   = i0 + orow;
            const float si   = sqi[orow];
            float o[4];
            #pragma unroll
            for (int cc = 0; cc < 4; ++cc)
                o[cc] = sqrtf(fmaxf(si + sqj[4 * jg + cc] - 2.f * d[rr][cc], EPSV));
            *reinterpret_cast<float4*>(&g_D[gi * N + j0 + 4 * jg]) =
                make_float4(o[0], o[1], o[2], o[3]);
            if (ti != tj) {
                #pragma unroll
                for (int cc = 0; cc < 4; ++cc)
                    g_D[(j0 + 4 * jg + cc) * N + gi] = o[cc];
            }
        }
    }
    // bar.sync gives CTA-wide happens-before into thread-0's release
    __syncthreads();
    if (tid == 0) {
        red_release(&g_stripe[ti]);
        if (ti != tj) red_release(&g_stripe[tj]);
    }

    if (bid >= CONS) return;             // producer-only blocks

    // =================== PHASE 2 setup (y has no g_D dependency) ===============
    const int   wa   = warp >> 2;        // anchor slot 0..3
    const int   sub  = warp & 3;         // column quarter
    const int   a    = bid * 4 + wa;
    const float INF  = __int_as_float(0x7f800000);

    const int idx = 128 * sub + 4 * lane;
    const int  ya = __ldg(&y[a]);        // prefetch before spin
    const int4 yv = *reinterpret_cast<const int4*>(y + idx);

    // =================== wait for this block's anchor stripe ===================
    if (tid == 0) {
        const unsigned* ctr = &g_stripe[bid >> 3];
        if (ldacq(ctr) < 32u) {
            do { __nanosleep(200); } while (ldacq(ctr) < 32u);
        }
    }
    __syncthreads();                     // publishes the acquire to the CTA

    // =================== PHASE 2: 4 anchors, 4 warps each ===================
    float (*posQ)[4][64] = reinterpret_cast<float(*)[4][64]>(pool + OFF_POSQ);
    int*   qcnt  = reinterpret_cast<int*>(pool + OFF_QCNT);
    int*   qsame = reinterpret_cast<int*>(pool + OFF_QSAM);
    float* wacc  = reinterpret_cast<float*>(pool + OFF_WACC);
    int*   lastp = reinterpret_cast<int*>(pool + OFF_LAST);

    const float cref = __ldcg(&g_D[a * N + ((a + 1) & (N - 1))]) * KLOG2E;
    const float4 xv  = __ldcg(reinterpret_cast<const float4*>(&g_D[a * N + idx]));
    const int   yl[4] = {yv.x, yv.y, yv.z, yv.w};
    const float xa[4] = {xv.x * KLOG2E, xv.y * KLOG2E, xv.z * KLOG2E, xv.w * KLOG2E};

    int cnt = 0, same = 0;
    #pragma unroll
    for (int i = 0; i < 4; ++i) {
        const int  j  = idx + i;
        const bool sc = (yl[i] == ya);
        const bool v  = sc && (j != a);
        const unsigned ms = __ballot_sync(0xffffffffu, sc);
        const unsigned mv = __ballot_sync(0xffffffffu, v);
        if (v) {
            const int slot = cnt + __popc(mv & ((1u << lane) - 1u));
            posQ[wa][sub][slot] = fminf(fmaxf(ex2a(cref - xa[i]), 1e-30f), 1e30f);
        }
        cnt  += __popc(mv);
        same += __popc(ms);
    }
    if (lane == 0) { qcnt[wa * 4 + sub] = cnt; qsame[wa * 4 + sub] = same; }

    float ex[4];
    #pragma unroll
    for (int i = 0; i < 4; ++i)
        ex[i] = (yl[i] == ya) ? INF : fmaxf(ex2a(xa[i] - cref), 1e-30f);

    __syncthreads();

    float ac0 = 0.f, ac1 = 0.f, ac2 = 0.f, ac3 = 0.f;
    #pragma unroll
    for (int q = 0; q < 4; ++q) {
        const int c = qcnt[wa * 4 + q];
        const float* pl = posQ[wa][q];
        for (int p = 0; p < c; ++p) {
            const float rp = pl[p];
            ac0 += rcpa(fmaf(ex[0], rp, 1.f));
            ac1 += rcpa(fmaf(ex[1], rp, 1.f));
            ac2 += rcpa(fmaf(ex[2], rp, 1.f));
            ac3 += rcpa(fmaf(ex[3], rp, 1.f));
        }
    }
    float acc = (ac0 + ac1) + (ac2 + ac3);
    #pragma unroll
    for (int o = 16; o > 0; o >>= 1) acc += __shfl_xor_sync(0xffffffffu, acc, o);
    if (lane == 0) wacc[warp] = acc;
    __syncthreads();

    if (tid == 0) {
        float s = 0.f;
        #pragma unroll
        for (int w = 0; w < 16; ++w) s += wacc[w];
        float cc = 0.f;
        #pragma unroll
        for (int q = 0; q < 4; ++q) {
            const int np = qcnt[q*4+0] + qcnt[q*4+1] + qcnt[q*4+2] + qcnt[q*4+3];
            const int sm = qsame[q*4+0] + qsame[q*4+1] + qsame[q*4+2] + qsame[q*4+3];
            cc += (float)(np * (N - sm));
        }
        g_partial[bid] = s;
        g_pcount[bid]  = cc;
        const unsigned t = atom_acqrel(&g_done);
        *lastp = (t == CONS - 1);
    }
    __syncthreads();

    // ======= FINAL REDUCE (last consumer block, single warp, no barriers) =======
    if (*lastp && warp == 0) {
        const float4* p4 = reinterpret_cast<const float4*>(g_partial);
        const float4* c4 = reinterpret_cast<const float4*>(g_pcount);
        const float4 s0 = __ldcg(&p4[lane]);          // 32 lanes x 4 = 128
        const float4 n0 = __ldcg(&c4[lane]);
        float s = (s0.x + s0.y) + (s0.z + s0.w);
        float n = (n0.x + n0.y) + (n0.z + n0.w);
        #pragma unroll
        for (int o = 16; o > 0; o >>= 1) {
            s += __shfl_xor_sync(0xffffffffu, s, o);
            n += __shfl_xor_sync(0xffffffffu, n, o);
        }
        if (lane == 0) {
            out[0] = s / n;
            g_done = 0;                               // reset for next replay
        }
        if (lane < 16) g_stripe[lane] = 0;
    }
}

// ---------------------------------------------------------------------------
extern "C" void kernel_launch(void* const* d_in, const int* in_sizes, int n_in,
                              void* d_out, int out_size) {
    const float* feat = (const float*)d_in[0];
    // d_in[1] = logits (unused by the loss)
    const int*   y    = (const int*)d_in[2];
    float*       out  = (float*)d_out;

    k_fused<<<NBLK, 512>>>(feat, y, out);
}

// round 16
// speedup vs baseline: 1.0107x; 1.0107x over previous
#include <cuda_runtime.h>
#include <cuda_bf16.h>

#define N      512
#define DIM    256
#define EPSV   1e-12f
#define KLOG2E 14.426950408889634f   // SCAL(=10) * log2(e)

#define NTILE  136                   // 16*17/2 triangular 32x32 tiles
#define NQBLK  544                   // 4 quarter-tiles (16x16) per tile
#define TBLK   256                   // triplet blocks (2 anchors each)
#define AP     36                    // As row pitch (floats), mult of 4 (16B LDS.128 align)
#define BP     18                    // Bt row pitch (floats), even (8B LDS.64 align)

__device__ float    g_D[N * N];
__device__ float    g_partial[TBLK];
__device__ float    g_pcount[TBLK];
__device__ unsigned g_done = 0;

typedef unsigned long long ull;

__device__ __forceinline__ ull ffma2(ull a, ull b, ull c) {
    ull d; asm("fma.rn.f32x2 %0, %1, %2, %3;" : "=l"(d) : "l"(a), "l"(b), "l"(c));
    return d;
}
__device__ __forceinline__ ull addf2(ull a, ull b) {
    ull d; asm("add.rn.f32x2 %0, %1, %2;" : "=l"(d) : "l"(a), "l"(b));
    return d;
}
__device__ __forceinline__ void unpack2(ull v, float& lo, float& hi) {
    asm("mov.b64 {%0, %1}, %2;" : "=f"(lo), "=f"(hi) : "l"(v));
}
__device__ __forceinline__ float ex2a(float x) {
    float y; asm("ex2.approx.ftz.f32 %0, %1;" : "=f"(y) : "f"(x)); return y;
}
__device__ __forceinline__ float rcpa(float x) {
    float y; asm("rcp.approx.ftz.f32 %0, %1;" : "=f"(y) : "f"(x)); return y;
}

// ---------------------------------------------------------------------------
// Kernel 1: 16x16 quarter-tiles of the lower triangle. 544 blocks x 256 thr
// (~3.7 blocks/SM -> ~30 warps/SM vs 16 before). Thread = (kq, si, sj):
// 2x2 f32x2 microtile over a 64-k quarter. A staged k-major duplicated (a,a)
// [2-way store conflicts], B k-major [conflict-free]. Mirror-write if ti!=tj.
// ---------------------------------------------------------------------------
__global__ void __launch_bounds__(256)
k_dist(const float* __restrict__ feat) {
    __shared__ __align__(16) float As[4][16][AP];   // 9216 B (dup pairs)
    __shared__ __align__(16) float Bt[4][16][BP];   // 4608 B
    __shared__ float sqi[16], sqj[16];
    __shared__ ull   stg[3][64][2];                 // 3072 B (kq combine)

    const int tid = threadIdx.x;
    const int bid = blockIdx.x;

    // decode bid -> tile (ti,tj) with ti>=tj, plus quarter (qi,qj)
    const int tb = bid >> 2;
    const int qi = (bid >> 1) & 1;
    const int qj = bid & 1;
    int ti = (int)((sqrtf(8.f * tb + 1.f) - 1.f) * 0.5f);
    if ((ti + 1) * (ti + 2) / 2 <= tb) ++ti;
    if (ti * (ti + 1) / 2 > tb) --ti;
    const int tj = tb - ti * (ti + 1) / 2;
    const int i0 = ti * 32 + qi * 16;
    const int j0 = tj * 32 + qj * 16;

    const float4* f4 = reinterpret_cast<const float4*>(feat);   // row pitch 64

    {   // squared norms: 32 rows, 8 threads/row
        const int r = tid >> 3, q = tid & 7;
        const int grow = (r < 16) ? (i0 + r) : (j0 + r - 16);
        float s = 0.f;
        #pragma unroll
        for (int u = 0; u < 8; ++u) {
            const float4 v = __ldg(&f4[grow * 64 + q * 8 + u]);
            s += v.x * v.x + v.y * v.y + v.z * v.z + v.w * v.w;
        }
        s += __shfl_xor_sync(0xffffffffu, s, 1);
        s += __shfl_xor_sync(0xffffffffu, s, 2);
        s += __shfl_xor_sync(0xffffffffu, s, 4);
        if (q == 0) { if (r < 16) sqi[r] = s; else sqj[r - 16] = s; }
    }

    const int kq      = tid >> 6;         // k quarter 0..3 (64 k each)
    const int spatial = tid & 63;
    const int si      = spatial >> 3;     // rows 2si, 2si+1   (0..7)
    const int sj      = spatial & 7;      // cols 2sj, 2sj+1   (0..7)

    // staging map: quarter qs = tid>>6, row = (tid>>2)&15, kfl = tid&3
    const int qs   = tid >> 6;
    const int rowS = (tid >> 2) & 15;
    const int kfl  = tid & 3;

    ull acc0 = 0, acc1 = 0;               // (row 2si | cols 2sj,2sj+1), (row 2si+1 | ...)

    // prefetch chunk 0 (each chunk stages 16 k per quarter)
    float4 pfa = __ldg(&f4[(i0 + rowS) * 64 + qs * 16 + kfl]);
    float4 pfb = __ldg(&f4[(j0 + rowS) * 64 + qs * 16 + kfl]);

    for (int c = 0; c < 4; ++c) {
        __syncthreads();
        {
            const float av[4] = {pfa.x, pfa.y, pfa.z, pfa.w};
            const float bv[4] = {pfb.x, pfb.y, pfb.z, pfb.w};
            #pragma unroll
            for (int e = 0; e < 4; ++e) {
                As[qs][4 * kfl + e][2 * rowS]     = av[e];
                As[qs][4 * kfl + e][2 * rowS + 1] = av[e];
                Bt[qs][4 * kfl + e][rowS]         = bv[e];
            }
        }
        __syncthreads();
        if (c < 3) {
            pfa = __ldg(&f4[(i0 + rowS) * 64 + qs * 16 + (c + 1) * 4 + kfl]);
            pfb = __ldg(&f4[(j0 + rowS) * 64 + qs * 16 + (c + 1) * 4 + kfl]);
        }
        const float* Ab = &As[kq][0][4 * si];
        const float* Bb = &Bt[kq][0][2 * sj];
        #pragma unroll
        for (int k = 0; k < 16; ++k) {
            const ulonglong2 a = *reinterpret_cast<const ulonglong2*>(Ab + k * AP);
            const ull        b = *reinterpret_cast<const ull*>(Bb + k * BP);
            acc0 = ffma2(a.x, b, acc0);
            acc1 = ffma2(a.y, b, acc1);
        }
    }

    // combine the 4 k-quarters
    __syncthreads();
    if (kq >= 1) {
        *reinterpret_cast<ulonglong2*>(&stg[kq - 1][spatial][0]) =
            make_ulonglong2(acc0, acc1);
    }
    __syncthreads();
    if (kq == 0) {
        #pragma unroll
        for (int s = 0; s < 3; ++s) {
            const ulonglong2 p = *reinterpret_cast<const ulonglong2*>(&stg[s][spatial][0]);
            acc0 = addf2(acc0, p.x);
            acc1 = addf2(acc1, p.y);
        }
        float d[2][2];
        unpack2(acc0, d[0][0], d[0][1]);
        unpack2(acc1, d[1][0], d[1][1]);
        #pragma unroll
        for (int rr = 0; rr < 2; ++rr) {
            const int   gi = i0 + 2 * si + rr;
            const float sI = sqi[2 * si + rr];
            float2 o;
            o.x = sqrtf(fmaxf(sI + sqj[2 * sj]     - 2.f * d[rr][0], EPSV));
            o.y = sqrtf(fmaxf(sI + sqj[2 * sj + 1] - 2.f * d[rr][1], EPSV));
            *reinterpret_cast<float2*>(&g_D[gi * N + j0 + 2 * sj]) = o;
            if (ti != tj) {
                g_D[(j0 + 2 * sj)     * N + gi] = o.x;
                g_D[(j0 + 2 * sj + 1) * N + gi] = o.y;
            }
        }
    }
}

// ---------------------------------------------------------------------------
// Kernel 2 (R12, proven): triplet sums, 256 blocks x 256 threads,
// 2 anchors/block, 4 warps per anchor; single-warp shuffle tail reduce.
// ---------------------------------------------------------------------------
__global__ void __launch_bounds__(256)
k_triplet(const int* __restrict__ y, float* __restrict__ out) {
    __shared__ float posR[2][4][48];
    __shared__ int   qcnt[2][4], qsame[2][4];
    __shared__ float wacc[8];
    __shared__ int   last_s;

    const int tid  = threadIdx.x;
    const int bid  = blockIdx.x;
    const int warp = tid >> 5;
    const int lane = tid & 31;
    const int q    = warp >> 2;           // anchor slot 0/1
    const int r    = warp & 3;            // column region 0..3
    const int a    = bid * 2 + q;
    const float INF = __int_as_float(0x7f800000);

    const int   ya   = __ldg(&y[a]);
    const float cref = __ldcg(&g_D[a * N + ((a + 1) & (N - 1))]) * KLOG2E;

    const int idx = 128 * r + 4 * lane;
    const int4   yv = *reinterpret_cast<const int4*>(y + idx);
    const float4 xv = __ldcg(reinterpret_cast<const float4*>(&g_D[a * N + idx]));
    const int   yl[4] = {yv.x, yv.y, yv.z, yv.w};
    const float xa[4] = {xv.x * KLOG2E, xv.y * KLOG2E, xv.z * KLOG2E, xv.w * KLOG2E};

    int cnt = 0, same = 0;
    #pragma unroll
    for (int i = 0; i < 4; ++i) {
        const int  j  = idx + i;
        const bool sc = (yl[i] == ya);
        const bool v  = sc && (j != a);
        const unsigned ms = __ballot_sync(0xffffffffu, sc);
        const unsigned mv = __ballot_sync(0xffffffffu, v);
        if (v) {
            const int slot = cnt + __popc(mv & ((1u << lane) - 1u));
            if (slot < 48)
                posR[q][r][slot] = fminf(fmaxf(ex2a(cref - xa[i]), 1e-30f), 1e30f);
        }
        cnt  += __popc(mv);
        same += __popc(ms);
    }
    if (lane == 0) { qcnt[q][r] = (cnt < 48) ? cnt : 48; qsame[q][r] = same; }

    float ex[4];
    #pragma unroll
    for (int i = 0; i < 4; ++i)
        ex[i] = (yl[i] == ya) ? INF : fmaxf(ex2a(xa[i] - cref), 1e-30f);

    __syncthreads();

    float ac0 = 0.f, ac1 = 0.f, ac2 = 0.f, ac3 = 0.f;
    #pragma unroll
    for (int r2 = 0; r2 < 4; ++r2) {
        const int    c  = qcnt[q][r2];
        const float* pl = posR[q][r2];
        for (int p = 0; p < c; ++p) {
            const float rp = pl[p];
            ac0 += rcpa(fmaf(ex[0], rp, 1.f));
            ac1 += rcpa(fmaf(ex[1], rp, 1.f));
            ac2 += rcpa(fmaf(ex[2], rp, 1.f));
            ac3 += rcpa(fmaf(ex[3], rp, 1.f));
        }
    }
    float acc = (ac0 + ac1) + (ac2 + ac3);
    #pragma unroll
    for (int o = 16; o > 0; o >>= 1) acc += __shfl_xor_sync(0xffffffffu, acc, o);
    if (lane == 0) wacc[warp] = acc;
    __syncthreads();

    if (tid == 0) {
        float s = 0.f;
        #pragma unroll
        for (int w = 0; w < 8; ++w) s += wacc[w];
        const int np0 = qcnt[0][0] + qcnt[0][1] + qcnt[0][2] + qcnt[0][3];
        const int sm0 = qsame[0][0] + qsame[0][1] + qsame[0][2] + qsame[0][3];
        const int np1 = qcnt[1][0] + qcnt[1][1] + qcnt[1][2] + qcnt[1][3];
        const int sm1 = qsame[1][0] + qsame[1][1] + qsame[1][2] + qsame[1][3];
        g_partial[bid] = s;
        g_pcount[bid]  = (float)(np0 * (N - sm0) + np1 * (N - sm1));
        __threadfence();
        const unsigned t = atomicAdd(&g_done, 1u);
        last_s = (t == TBLK - 1);
    }
    __syncthreads();

    if (last_s && warp == 0) {
        __threadfence();
        const float4* p4 = reinterpret_cast<const float4*>(g_partial);
        const float4* c4 = reinterpret_cast<const float4*>(g_pcount);
        const float4 s0 = __ldcg(&p4[2 * lane]);
        const float4 s1 = __ldcg(&p4[2 * lane + 1]);
        const float4 n0 = __ldcg(&c4[2 * lane]);
        const float4 n1 = __ldcg(&c4[2 * lane + 1]);
        float s = ((s0.x + s0.y) + (s0.z + s0.w)) + ((s1.x + s1.y) + (s1.z + s1.w));
        float n = ((n0.x + n0.y) + (n0.z + n0.w)) + ((n1.x + n1.y) + (n1.z + n1.w));
        #pragma unroll
        for (int o = 16; o > 0; o >>= 1) {
            s += __shfl_xor_sync(0xffffffffu, s, o);
            n += __shfl_xor_sync(0xffffffffu, n, o);
        }
        if (lane == 0) {
            out[0] = s / n;
            g_done = 0;                   // reset for next graph replay
        }
    }
}

// ---------------------------------------------------------------------------
extern "C" void kernel_launch(void* const* d_in, const int* in_sizes, int n_in,
                              void* d_out, int out_size) {
    const float* feat = (const float*)d_in[0];
    // d_in[1] = logits (unused by the loss)
    const int*   y    = (const int*)d_in[2];
    float*       out  = (float*)d_out;

    k_dist   <<<NQBLK, 256>>>(feat);
    k_triplet<<<TBLK,  256>>>(y, out);
}

// round 17
// speedup vs baseline: 1.2557x; 1.2424x over previous
#include <cuda_runtime.h>
#include <cuda_bf16.h>

#define N      512
#define DIM    256
#define EPSV   1e-12f
#define KLOG2E 14.426950408889634f   // SCAL(=10) * log2(e)

#define NTRI   136                   // 16*17/2 triangular 32x32 tiles
#define TBLK   256                   // triplet blocks (2 anchors each)
#define APITCH 68
#define BPITCH 36

__device__ float    g_D[N * N];
__device__ float    g_partial[TBLK];
__device__ float    g_pcount[TBLK];
__device__ unsigned g_done = 0;

typedef unsigned long long ull;

__device__ __forceinline__ ull ffma2(ull a, ull b, ull c) {
    ull d; asm("fma.rn.f32x2 %0, %1, %2, %3;" : "=l"(d) : "l"(a), "l"(b), "l"(c));
    return d;
}
__device__ __forceinline__ ull addf2(ull a, ull b) {
    ull d; asm("add.rn.f32x2 %0, %1, %2;" : "=l"(d) : "l"(a), "l"(b));
    return d;
}
__device__ __forceinline__ void unpack2(ull v, float& lo, float& hi) {
    asm("mov.b64 {%0, %1}, %2;" : "=f"(lo), "=f"(hi) : "l"(v));
}
__device__ __forceinline__ float ex2a(float x) {
    float y; asm("ex2.approx.ftz.f32 %0, %1;" : "=f"(y) : "f"(x)); return y;
}
__device__ __forceinline__ float rcpa(float x) {
    float y; asm("rcp.approx.ftz.f32 %0, %1;" : "=f"(y) : "f"(x)); return y;
}
__device__ __forceinline__ unsigned atom_acqrel(unsigned* p) {
    unsigned old;
    asm volatile("atom.acq_rel.gpu.global.add.u32 %0, [%1], %2;"
                 : "=r"(old) : "l"(p), "r"(1u) : "memory");
    return old;
}

// ---------------------------------------------------------------------------
// Kernel 1 (R9/R12, proven): lower-triangle 32x32 distance tiles, f32x2 FMA,
// 136 blocks x 512 threads (4 k-quarters per thread group).
// ---------------------------------------------------------------------------
__global__ void __launch_bounds__(512)
k_dist(const float* __restrict__ feat) {
    __shared__ __align__(16) float Ad[4][16][APITCH];
    __shared__ __align__(16) float Bt[4][16][BPITCH];
    __shared__ float sqi[32], sqj[32];
    __shared__ ull   stg[3][128][4];

    const int tid = threadIdx.x;
    const int bid = blockIdx.x;

    int ti = (int)((sqrtf(8.f * bid + 1.f) - 1.f) * 0.5f);
    if ((ti + 1) * (ti + 2) / 2 <= bid) ++ti;
    if (ti * (ti + 1) / 2 > bid) --ti;
    const int tj = bid - ti * (ti + 1) / 2;
    const int i0 = ti * 32, j0 = tj * 32;

    const float4* f4 = reinterpret_cast<const float4*>(feat);

    {   // squared norms: 64 rows, 8 threads/row
        const int r = tid >> 3, q = tid & 7;
        const int grow = (r < 32) ? (i0 + r) : (j0 + r - 32);
        float s = 0.f;
        #pragma unroll
        for (int u = 0; u < 8; ++u) {
            const float4 v = __ldg(&f4[grow * 64 + q * 8 + u]);
            s += v.x * v.x + v.y * v.y + v.z * v.z + v.w * v.w;
        }
        s += __shfl_xor_sync(0xffffffffu, s, 1);
        s += __shfl_xor_sync(0xffffffffu, s, 2);
        s += __shfl_xor_sync(0xffffffffu, s, 4);
        if (q == 0) { if (r < 32) sqi[r] = s; else sqj[r - 32] = s; }
    }

    const int kq = tid >> 7;
    const int r7 = tid & 127;
    const int ig = r7 & 15;
    const int jg = r7 >> 4;
    const int row = r7 >> 2;
    const int kf  = r7 & 3;

    ull acc00 = 0, acc01 = 0, acc10 = 0, acc11 = 0;

    float4 pfa = __ldg(&f4[(i0 + row) * 64 + kq * 16 + kf]);
    float4 pfb = __ldg(&f4[(j0 + row) * 64 + kq * 16 + kf]);

    for (int c = 0; c < 4; ++c) {
        __syncthreads();
        {
            const float av[4] = {pfa.x, pfa.y, pfa.z, pfa.w};
            const float bv[4] = {pfb.x, pfb.y, pfb.z, pfb.w};
            #pragma unroll
            for (int e = 0; e < 4; ++e) {
                Ad[kq][4 * kf + e][2 * row]     = av[e];
                Ad[kq][4 * kf + e][2 * row + 1] = av[e];
                Bt[kq][4 * kf + e][row]         = bv[e];
            }
        }
        __syncthreads();
        if (c < 3) {
            pfa = __ldg(&f4[(i0 + row) * 64 + kq * 16 + (c + 1) * 4 + kf]);
            pfb = __ldg(&f4[(j0 + row) * 64 + kq * 16 + (c + 1) * 4 + kf]);
        }
        const float* Ab = &Ad[kq][0][4 * ig];
        const float* Bb = &Bt[kq][0][4 * jg];
        #pragma unroll
        for (int k = 0; k < 16; ++k) {
            const ulonglong2 a = *reinterpret_cast<const ulonglong2*>(Ab + k * APITCH);
            const ulonglong2 b = *reinterpret_cast<const ulonglong2*>(Bb + k * BPITCH);
            acc00 = ffma2(a.x, b.x, acc00);
            acc01 = ffma2(a.x, b.y, acc01);
            acc10 = ffma2(a.y, b.x, acc10);
            acc11 = ffma2(a.y, b.y, acc11);
        }
    }

    __syncthreads();
    if (kq >= 1) {
        stg[kq - 1][r7][0] = acc00; stg[kq - 1][r7][1] = acc01;
        stg[kq - 1][r7][2] = acc10; stg[kq - 1][r7][3] = acc11;
    }
    __syncthreads();
    if (kq == 0) {
        #pragma unroll
        for (int s = 0; s < 3; ++s) {
            acc00 = addf2(acc00, stg[s][r7][0]);
            acc01 = addf2(acc01, stg[s][r7][1]);
            acc10 = addf2(acc10, stg[s][r7][2]);
            acc11 = addf2(acc11, stg[s][r7][3]);
        }
        float d[2][4];
        unpack2(acc00, d[0][0], d[0][1]); unpack2(acc01, d[0][2], d[0][3]);
        unpack2(acc10, d[1][0], d[1][1]); unpack2(acc11, d[1][2], d[1][3]);
        #pragma unroll
        for (int rr = 0; rr < 2; ++rr) {
            const int   orow = 2 * ig + rr;
            const float si   = sqi[orow];
            float o[4];
            #pragma unroll
            for (int cc = 0; cc < 4; ++cc)
                o[cc] = sqrtf(fmaxf(si + sqj[4 * jg + cc] - 2.f * d[rr][cc], EPSV));
            *reinterpret_cast<float4*>(&g_D[(i0 + orow) * N + j0 + 4 * jg]) =
                make_float4(o[0], o[1], o[2], o[3]);
            if (ti != tj) {
                #pragma unroll
                for (int cc = 0; cc < 4; ++cc)
                    g_D[(j0 + 4 * jg + cc) * N + i0 + orow] = o[cc];
            }
        }
    }
}

// ---------------------------------------------------------------------------
// Kernel 2 (R12, proven; tail sync via acq_rel instead of __threadfence):
// 256 blocks x 256 threads, 2 anchors/block, 4 warps per anchor;
// single-warp shuffle tail reduce.
// ---------------------------------------------------------------------------
__global__ void __launch_bounds__(256)
k_triplet(const int* __restrict__ y, float* __restrict__ out) {
    __shared__ float posR[2][4][48];
    __shared__ int   qcnt[2][4], qsame[2][4];
    __shared__ float wacc[8];
    __shared__ int   last_s;

    const int tid  = threadIdx.x;
    const int bid  = blockIdx.x;
    const int warp = tid >> 5;
    const int lane = tid & 31;
    const int q    = warp >> 2;           // anchor slot 0/1
    const int r    = warp & 3;            // column region 0..3
    const int a    = bid * 2 + q;
    const float INF = __int_as_float(0x7f800000);

    const int   ya   = __ldg(&y[a]);
    const float cref = __ldcg(&g_D[a * N + ((a + 1) & (N - 1))]) * KLOG2E;

    const int idx = 128 * r + 4 * lane;
    const int4   yv = *reinterpret_cast<const int4*>(y + idx);
    const float4 xv = __ldcg(reinterpret_cast<const float4*>(&g_D[a * N + idx]));
    const int   yl[4] = {yv.x, yv.y, yv.z, yv.w};
    const float xa[4] = {xv.x * KLOG2E, xv.y * KLOG2E, xv.z * KLOG2E, xv.w * KLOG2E};

    int cnt = 0, same = 0;
    #pragma unroll
    for (int i = 0; i < 4; ++i) {
        const int  j  = idx + i;
        const bool sc = (yl[i] == ya);
        const bool v  = sc && (j != a);
        const unsigned ms = __ballot_sync(0xffffffffu, sc);
        const unsigned mv = __ballot_sync(0xffffffffu, v);
        if (v) {
            const int slot = cnt + __popc(mv & ((1u << lane) - 1u));
            if (slot < 48)
                posR[q][r][slot] = fminf(fmaxf(ex2a(cref - xa[i]), 1e-30f), 1e30f);
        }
        cnt  += __popc(mv);
        same += __popc(ms);
    }
    if (lane == 0) { qcnt[q][r] = (cnt < 48) ? cnt : 48; qsame[q][r] = same; }

    float ex[4];
    #pragma unroll
    for (int i = 0; i < 4; ++i)
        ex[i] = (yl[i] == ya) ? INF : fmaxf(ex2a(xa[i] - cref), 1e-30f);

    __syncthreads();

    float ac0 = 0.f, ac1 = 0.f, ac2 = 0.f, ac3 = 0.f;
    #pragma unroll
    for (int r2 = 0; r2 < 4; ++r2) {
        const int    c  = qcnt[q][r2];
        const float* pl = posR[q][r2];
        for (int p = 0; p < c; ++p) {
            const float rp = pl[p];
            ac0 += rcpa(fmaf(ex[0], rp, 1.f));
            ac1 += rcpa(fmaf(ex[1], rp, 1.f));
            ac2 += rcpa(fmaf(ex[2], rp, 1.f));
            ac3 += rcpa(fmaf(ex[3], rp, 1.f));
        }
    }
    float acc = (ac0 + ac1) + (ac2 + ac3);
    #pragma unroll
    for (int o = 16; o > 0; o >>= 1) acc += __shfl_xor_sync(0xffffffffu, acc, o);
    if (lane == 0) wacc[warp] = acc;
    __syncthreads();

    if (tid == 0) {
        float s = 0.f;
        #pragma unroll
        for (int w = 0; w < 8; ++w) s += wacc[w];
        const int np0 = qcnt[0][0] + qcnt[0][1] + qcnt[0][2] + qcnt[0][3];
        const int sm0 = qsame[0][0] + qsame[0][1] + qsame[0][2] + qsame[0][3];
        const int np1 = qcnt[1][0] + qcnt[1][1] + qcnt[1][2] + qcnt[1][3];
        const int sm1 = qsame[1][0] + qsame[1][1] + qsame[1][2] + qsame[1][3];
        g_partial[bid] = s;
        g_pcount[bid]  = (float)(np0 * (N - sm0) + np1 * (N - sm1));
        // acq_rel atomic: release-orders the partial stores, no L1 flush
        const unsigned t = atom_acqrel(&g_done);
        last_s = (t == TBLK - 1);
    }
    __syncthreads();

    // single-warp tail reduce (no barriers): 256 partials = 8 per lane
    if (last_s && warp == 0) {
        const float4* p4 = reinterpret_cast<const float4*>(g_partial);
        const float4* c4 = reinterpret_cast<const float4*>(g_pcount);
        const float4 s0 = __ldcg(&p4[2 * lane]);
        const float4 s1 = __ldcg(&p4[2 * lane + 1]);
        const float4 n0 = __ldcg(&c4[2 * lane]);
        const float4 n1 = __ldcg(&c4[2 * lane + 1]);
        float s = ((s0.x + s0.y) + (s0.z + s0.w)) + ((s1.x + s1.y) + (s1.z + s1.w));
        float n = ((n0.x + n0.y) + (n0.z + n0.w)) + ((n1.x + n1.y) + (n1.z + n1.w));
        #pragma unroll
        for (int o = 16; o > 0; o >>= 1) {
            s += __shfl_xor_sync(0xffffffffu, s, o);
            n += __shfl_xor_sync(0xffffffffu, n, o);
        }
        if (lane == 0) {
            out[0] = s / n;
            g_done = 0;                   // reset for next graph replay
        }
    }
}

// ---------------------------------------------------------------------------
extern "C" void kernel_launch(void* const* d_in, const int* in_sizes, int n_in,
                              void* d_out, int out_size) {
    const float* feat = (const float*)d_in[0];
    // d_in[1] = logits (unused by the loss)
    const int*   y    = (const int*)d_in[2];
    float*       out  = (float*)d_out;

    k_dist   <<<NTRI, 512>>>(feat);
    k_triplet<<<TBLK, 256>>>(y, out);
}